// round 6
// baseline (speedup 1.0000x reference)
#include <cuda_runtime.h>
#include <math.h>
#include <stdint.h>

#define NN 100000
#define EE 1200000
#define BB 64
#define NSTEPS 6
#define GRID_M 782   // ceil(NN/128)

__device__ float g_h[NN * 64];
__device__ float g_h0[NN * 64];
__device__ float g_a[NN * 64];
__device__ int   g_rowstart[NN + 1];
__device__ int   g_cursor[NN];
__device__ int   g_eidx[EE];
__device__ int   g_cnt4[NN * 4];
__device__ float g_BredH[16384], g_BredL[16384];     // reduce_W: 2 stages x (K=128,N=64)
__device__ float g_BedgeH[16384], g_BedgeL[16384];   // stacked edge_W: 2 stages
__device__ float g_BgruH[32768], g_BgruL[32768];     // 4 gates x (K=128,N=64)
__device__ float g_gate[NN];
__device__ float g_gmax[BB];
__device__ float g_den[BB];
__device__ float g_rsum[BB * 128];

__device__ __forceinline__ float tf32r(float x){ float y; asm("cvt.rna.tf32.f32 %0,%1;":"=f"(y):"f"(x)); return y; }

// fragment-permuted indices (m16n8k8 tf32 mma.sync layouts), kcs = K/8 chunks
__device__ __forceinline__ int aidx(int row,int k,int kcs){
    int mt=row>>4, r=row&15;
    return (((mt*kcs+(k>>3))<<5) + (((r&7)<<2)+(k&3)))*4 + ((r>>3)+(((k>>2)&1)<<1));
}
__device__ __forceinline__ int bidx(int k,int n,int kcs){
    return ((((n>>3)*kcs+(k>>3))<<5) + (((n&7)<<2)+(k&3)))*2 + ((k>>2)&1);
}
__device__ __forceinline__ void mma8(float* c,const uint32_t* a,const uint32_t* b){
    asm volatile("mma.sync.aligned.m16n8k8.row.col.f32.tf32.tf32.f32 "
        "{%0,%1,%2,%3},{%4,%5,%6,%7},{%8,%9},{%0,%1,%2,%3};"
        : "+f"(c[0]),"+f"(c[1]),"+f"(c[2]),"+f"(c[3])
        : "r"(a[0]),"r"(a[1]),"r"(a[2]),"r"(a[3]),"r"(b[0]),"r"(b[1]));
}
// 3xTF32 compensated accumulate
__device__ __forceinline__ void mma3(float* c,const uint4& ah,const uint4& al,
                                     const uint2& bh,const uint2& bl){
    mma8(c,(const uint32_t*)&ah,(const uint32_t*)&bh);
    mma8(c,(const uint32_t*)&ah,(const uint32_t*)&bl);
    mma8(c,(const uint32_t*)&al,(const uint32_t*)&bh);
}
__device__ __forceinline__ void split2(float v,float& hi,float& lo){
    hi=tf32r(v); lo=tf32r(v-hi);
}

// smem: sAh 16384 | sAl 16384 | sBh 8192 | sBl 8192  (floats) = 196608 B
#define OAL 16384
#define OBH 32768
#define OBL 40960
#define SMB ((16384*2+8192*2)*4)

// ---------------- CSR build ----------------------------------------------------
__global__ void zero_cnt(){ int i=blockIdx.x*blockDim.x+threadIdx.x; if(i<NN*4) g_cnt4[i]=0; }
__global__ void hist_kernel(const int* __restrict__ dst,const int* __restrict__ ety){
    int e=blockIdx.x*blockDim.x+threadIdx.x; if(e<EE) atomicAdd(&g_cnt4[dst[e]*4+ety[e]],1);
}
__global__ void scan_kernel(){
    __shared__ int part[1024];
    int tid=threadIdx.x; const int CH=(NN+1023)/1024; int base=tid*CH; int s=0;
    for(int i=0;i<CH;++i){ int n=base+i; if(n<NN) s+=g_cnt4[n*4]+g_cnt4[n*4+1]+g_cnt4[n*4+2]+g_cnt4[n*4+3]; }
    part[tid]=s; __syncthreads();
    for(int off=1;off<1024;off<<=1){ int v=(tid>=off)?part[tid-off]:0; __syncthreads(); part[tid]+=v; __syncthreads(); }
    int run=(tid?part[tid-1]:0);
    for(int i=0;i<CH;++i){ int n=base+i; if(n<NN){ g_rowstart[n]=run; g_cursor[n]=run;
        run+=g_cnt4[n*4]+g_cnt4[n*4+1]+g_cnt4[n*4+2]+g_cnt4[n*4+3]; } }
    if(tid==1023) g_rowstart[NN]=part[1023];
}
__global__ void fill_kernel(const int* __restrict__ src,const int* __restrict__ dst,const int* __restrict__ ety){
    int e=blockIdx.x*blockDim.x+threadIdx.x;
    if(e<EE){ int pos=atomicAdd(&g_cursor[dst[e]],1); g_eidx[pos]=(src[e]<<2)|ety[e]; }
}

// ---------------- weight packing (hi/lo, perm layout, kcs=16 per stage) ----------
__global__ void pack_mma(const float* __restrict__ rW,const float* __restrict__ eW,
                         const float* __restrict__ Wi,const float* __restrict__ Wh){
    int i=blockIdx.x*blockDim.x+threadIdx.x; if(i>=65536) return;
    float v; int off;
    if(i<16384){                       // reduce_W [256][64]
        int k=i>>6,n=i&63; v=rW[k*64+n];
        off=(k>>7)*8192+bidx(k&127,n,16);
        float hi,lo; split2(v,hi,lo); g_BredH[off]=hi; g_BredL[off]=lo;
    }else if(i<32768){                 // stacked edge_W: k=t*64+h
        int q=i-16384; int k=q>>6,n=q&63;
        v=eW[(k>>6)*4096+(k&63)*64+n];
        off=(k>>7)*8192+bidx(k&127,n,16);
        float hi,lo; split2(v,hi,lo); g_BedgeH[off]=hi; g_BedgeL[off]=lo;
    }else{                             // gru gates: K=128 ([a|h]), N=64
        int q=i-32768; int gate=q>>13; q&=8191; int k=q>>6,n=q&63;
        if(gate==0)      v=(k<64)?Wi[n*64+k]:Wh[n*64+k-64];
        else if(gate==1) v=(k<64)?Wi[(64+n)*64+k]:Wh[(64+n)*64+k-64];
        else if(gate==2) v=(k<64)?Wi[(128+n)*64+k]:0.f;
        else             v=(k<64)?0.f:Wh[(128+n)*64+k-64];
        off=gate*8192+bidx(k,n,16);
        float hi,lo; split2(v,hi,lo); g_BgruH[off]=hi; g_BgruL[off]=lo;
    }
}

__device__ __forceinline__ void copyB(float* smf,const float* BH,const float* BL,int tid){
    for(int i=tid;i<2048;i+=1024){
        ((float4*)(smf+OBH))[i]=((const float4*)BH)[i];
        ((float4*)(smf+OBL))[i]=((const float4*)BL)[i];
    }
}

// ---------------- reduce: h0 = ann @ reduce_W + rb (3xTF32) ----------------------
__global__ __launch_bounds__(1024,1) void reduce_mma(const float* __restrict__ ann,const float* __restrict__ rb){
    extern __shared__ float smf[];
    const int tid=threadIdx.x; const int n0=blockIdx.x*128;
    const int w=tid>>5,lane=tid&31,mtile=w>>2,nt0=(w&3)*2;
    float C[2][4]={};
    for(int st=0;st<2;++st){
        for(int idx=tid;idx<4096;idx+=1024){
            int row=idx>>5,k=(idx&31)<<2; int n=n0+row;
            float4 v=make_float4(0,0,0,0);
            if(n<NN) v=*(const float4*)&ann[(size_t)n*256+st*128+k];
            float hi,lo;
            split2(v.x,hi,lo); smf[aidx(row,k+0,16)]=hi; smf[OAL+aidx(row,k+0,16)]=lo;
            split2(v.y,hi,lo); smf[aidx(row,k+1,16)]=hi; smf[OAL+aidx(row,k+1,16)]=lo;
            split2(v.z,hi,lo); smf[aidx(row,k+2,16)]=hi; smf[OAL+aidx(row,k+2,16)]=lo;
            split2(v.w,hi,lo); smf[aidx(row,k+3,16)]=hi; smf[OAL+aidx(row,k+3,16)]=lo;
        }
        copyB(smf,g_BredH+st*8192,g_BredL+st*8192,tid);
        __syncthreads();
        for(int kc=0;kc<16;++kc){
            uint4 ah=*(const uint4*)&smf[((mtile*16+kc)*32+lane)*4];
            uint4 al=*(const uint4*)&smf[OAL+((mtile*16+kc)*32+lane)*4];
#pragma unroll
            for(int j=0;j<2;++j){
                uint2 bh=*(const uint2*)&smf[OBH+(((nt0+j)*16+kc)*32+lane)*2];
                uint2 bl=*(const uint2*)&smf[OBL+(((nt0+j)*16+kc)*32+lane)*2];
                mma3(C[j],ah,al,bh,bl);
            }
        }
        __syncthreads();
    }
    const int g=lane>>2,tig=lane&3;
    int r0=n0+mtile*16+g, r1=r0+8;
#pragma unroll
    for(int j=0;j<2;++j){
        int cb=(nt0+j)*8+2*tig;
        float b0=rb[cb],b1=rb[cb+1];
        if(r0<NN){ float2 v={C[j][0]+b0,C[j][1]+b1};
            *(float2*)&g_h0[(size_t)r0*64+cb]=v; *(float2*)&g_h[(size_t)r0*64+cb]=v; }
        if(r1<NN){ float2 v={C[j][2]+b0,C[j][3]+b1};
            *(float2*)&g_h0[(size_t)r1*64+cb]=v; *(float2*)&g_h[(size_t)r1*64+cb]=v; }
    }
}

// ---------------- agg: a = per-type CSR sums @ edge_W + cnt*edge_b ---------------
__global__ __launch_bounds__(1024,1) void agg_mma(const float* __restrict__ eb){
    extern __shared__ float smf[];
    const int tid=threadIdx.x,w=tid>>5,lane=tid&31; const int n0=blockIdx.x*128;
    // gather: 4 nodes per warp; types 0,1 -> stage0 smem; types 2,3 kept in regs
    float2 st2[4],st3[4];
    for(int i=0;i<4;++i){
        int nloc=w*4+i, n=n0+nloc;
        float2 a0={0,0},a1={0,0},a2={0,0},a3={0,0};
        if(n<NN){
            int e=g_rowstart[n],re=g_rowstart[n+1];
            for(;e+2<=re;e+=2){
                int v0=g_eidx[e],v1=g_eidx[e+1];
                float2 x0=*(const float2*)&g_h[(size_t)(v0>>2)*64+(lane<<1)];
                float2 x1=*(const float2*)&g_h[(size_t)(v1>>2)*64+(lane<<1)];
                int t0=v0&3,t1=v1&3;
                if(t0==0){a0.x+=x0.x;a0.y+=x0.y;}else if(t0==1){a1.x+=x0.x;a1.y+=x0.y;}
                else if(t0==2){a2.x+=x0.x;a2.y+=x0.y;}else{a3.x+=x0.x;a3.y+=x0.y;}
                if(t1==0){a0.x+=x1.x;a0.y+=x1.y;}else if(t1==1){a1.x+=x1.x;a1.y+=x1.y;}
                else if(t1==2){a2.x+=x1.x;a2.y+=x1.y;}else{a3.x+=x1.x;a3.y+=x1.y;}
            }
            for(;e<re;++e){
                int v=g_eidx[e]; float2 x=*(const float2*)&g_h[(size_t)(v>>2)*64+(lane<<1)]; int t=v&3;
                if(t==0){a0.x+=x.x;a0.y+=x.y;}else if(t==1){a1.x+=x.x;a1.y+=x.y;}
                else if(t==2){a2.x+=x.x;a2.y+=x.y;}else{a3.x+=x.x;a3.y+=x.y;}
            }
        }
        int k=lane<<1; float hi,lo;
        split2(a0.x,hi,lo); smf[aidx(nloc,k,16)]=hi;      smf[OAL+aidx(nloc,k,16)]=lo;
        split2(a0.y,hi,lo); smf[aidx(nloc,k+1,16)]=hi;    smf[OAL+aidx(nloc,k+1,16)]=lo;
        split2(a1.x,hi,lo); smf[aidx(nloc,64+k,16)]=hi;   smf[OAL+aidx(nloc,64+k,16)]=lo;
        split2(a1.y,hi,lo); smf[aidx(nloc,64+k+1,16)]=hi; smf[OAL+aidx(nloc,64+k+1,16)]=lo;
        st2[i]=a2; st3[i]=a3;
    }
    const int mtile=w>>2,nt0=(w&3)*2;
    float C[2][4]={};
    for(int st=0;st<2;++st){
        if(st==1){
            for(int i=0;i<4;++i){
                int nloc=w*4+i,k=lane<<1; float hi,lo;
                split2(st2[i].x,hi,lo); smf[aidx(nloc,k,16)]=hi;      smf[OAL+aidx(nloc,k,16)]=lo;
                split2(st2[i].y,hi,lo); smf[aidx(nloc,k+1,16)]=hi;    smf[OAL+aidx(nloc,k+1,16)]=lo;
                split2(st3[i].x,hi,lo); smf[aidx(nloc,64+k,16)]=hi;   smf[OAL+aidx(nloc,64+k,16)]=lo;
                split2(st3[i].y,hi,lo); smf[aidx(nloc,64+k+1,16)]=hi; smf[OAL+aidx(nloc,64+k+1,16)]=lo;
            }
        }
        copyB(smf,g_BedgeH+st*8192,g_BedgeL+st*8192,tid);
        __syncthreads();
        for(int kc=0;kc<16;++kc){
            uint4 ah=*(const uint4*)&smf[((mtile*16+kc)*32+lane)*4];
            uint4 al=*(const uint4*)&smf[OAL+((mtile*16+kc)*32+lane)*4];
#pragma unroll
            for(int j=0;j<2;++j){
                uint2 bh=*(const uint2*)&smf[OBH+(((nt0+j)*16+kc)*32+lane)*2];
                uint2 bl=*(const uint2*)&smf[OBL+(((nt0+j)*16+kc)*32+lane)*2];
                mma3(C[j],ah,al,bh,bl);
            }
        }
        __syncthreads();
    }
    const int g=lane>>2,tig=lane&3;
    int r0=n0+mtile*16+g, r1=r0+8;
#pragma unroll
    for(int j=0;j<2;++j){
        int cb=(nt0+j)*8+2*tig;
        float e00=eb[cb],e01=eb[cb+1],e10=eb[64+cb],e11=eb[64+cb+1];
        float e20=eb[128+cb],e21=eb[128+cb+1],e30=eb[192+cb],e31=eb[192+cb+1];
        if(r0<NN){ int4 c=*(const int4*)&g_cnt4[r0*4];
            float2 v={C[j][0]+c.x*e00+c.y*e10+c.z*e20+c.w*e30,
                      C[j][1]+c.x*e01+c.y*e11+c.z*e21+c.w*e31};
            *(float2*)&g_a[(size_t)r0*64+cb]=v; }
        if(r1<NN){ int4 c=*(const int4*)&g_cnt4[r1*4];
            float2 v={C[j][2]+c.x*e00+c.y*e10+c.z*e20+c.w*e30,
                      C[j][3]+c.x*e01+c.y*e11+c.z*e21+c.w*e31};
            *(float2*)&g_a[(size_t)r1*64+cb]=v; }
    }
}

// ---------------- fused GRU: [a|h] @ 4 gate weights + nonlinearity ---------------
__global__ __launch_bounds__(1024,1) void gru_mma(const float* __restrict__ bi,const float* __restrict__ bh){
    extern __shared__ float smf[];
    const int tid=threadIdx.x; const int n0=blockIdx.x*128;
    for(int idx=tid;idx<4096;idx+=1024){
        int row=idx>>5,k=(idx&31)<<2; int n=n0+row;
        float4 v=make_float4(0,0,0,0);
        if(n<NN) v=(k<64)?*(const float4*)&g_a[(size_t)n*64+k]:*(const float4*)&g_h[(size_t)n*64+k-64];
        float hi,lo;
        split2(v.x,hi,lo); smf[aidx(row,k+0,16)]=hi; smf[OAL+aidx(row,k+0,16)]=lo;
        split2(v.y,hi,lo); smf[aidx(row,k+1,16)]=hi; smf[OAL+aidx(row,k+1,16)]=lo;
        split2(v.z,hi,lo); smf[aidx(row,k+2,16)]=hi; smf[OAL+aidx(row,k+2,16)]=lo;
        split2(v.w,hi,lo); smf[aidx(row,k+3,16)]=hi; smf[OAL+aidx(row,k+3,16)]=lo;
    }
    const int w=tid>>5,lane=tid&31,mtile=w>>2,nt0=(w&3)*2;
    float C[4][2][4]={};
    for(int gate=0;gate<4;++gate){
        copyB(smf,g_BgruH+gate*8192,g_BgruL+gate*8192,tid);
        __syncthreads();
        for(int kc=0;kc<16;++kc){
            uint4 ah=*(const uint4*)&smf[((mtile*16+kc)*32+lane)*4];
            uint4 al=*(const uint4*)&smf[OAL+((mtile*16+kc)*32+lane)*4];
#pragma unroll
            for(int j=0;j<2;++j){
                uint2 bhv=*(const uint2*)&smf[OBH+(((nt0+j)*16+kc)*32+lane)*2];
                uint2 blv=*(const uint2*)&smf[OBL+(((nt0+j)*16+kc)*32+lane)*2];
                mma3(C[gate][j],ah,al,bhv,blv);
            }
        }
        __syncthreads();
    }
    const int g=lane>>2,tig=lane&3;
    int r0=n0+mtile*16+g, r1=r0+8;
#pragma unroll
    for(int j=0;j<2;++j){
        int cb=(nt0+j)*8+2*tig;
        float br0=bi[cb]+bh[cb], br1=bi[cb+1]+bh[cb+1];
        float bz0=bi[64+cb]+bh[64+cb], bz1=bi[64+cb+1]+bh[64+cb+1];
        float bn0=bi[128+cb], bn1=bi[128+cb+1];
        float bm0=bh[128+cb], bm1=bh[128+cb+1];
#pragma unroll
        for(int half=0;half<2;++half){
            int row=half?r1:r0;
            if(row<NN){
                float2 ho=*(const float2*)&g_h[(size_t)row*64+cb];
                float r_0=1.f/(1.f+expf(-(C[0][j][half*2]+br0)));
                float r_1=1.f/(1.f+expf(-(C[0][j][half*2+1]+br1)));
                float z_0=1.f/(1.f+expf(-(C[1][j][half*2]+bz0)));
                float z_1=1.f/(1.f+expf(-(C[1][j][half*2+1]+bz1)));
                float n_0=tanhf(C[2][j][half*2]+bn0+r_0*(C[3][j][half*2]+bm0));
                float n_1=tanhf(C[2][j][half*2+1]+bn1+r_1*(C[3][j][half*2+1]+bm1));
                float2 hn={(1.f-z_0)*n_0+z_0*ho.x,(1.f-z_1)*n_1+z_1*ho.y};
                *(float2*)&g_h[(size_t)row*64+cb]=hn;
            }
        }
    }
}

// ---------------- attention pooling ----------------------------------------------
__device__ void atomicMaxFloat(float* addr,float v){
    int* ia=(int*)addr; int old=*ia;
    while(true){ float f=__int_as_float(old); if(f>=v) break;
        int as=old; old=atomicCAS(ia,as,__float_as_int(v)); if(old==as) break; }
}
__global__ void init_pool(){
    int tid=threadIdx.x;
    if(tid<BB){ g_gmax[tid]=__int_as_float(0xff800000); g_den[tid]=0.f; }
    for(int i=tid;i<BB*128;i+=256) g_rsum[i]=0.f;
}
__global__ __launch_bounds__(256) void gate_kernel(const int* __restrict__ gid,
        const float* __restrict__ gW,const float* __restrict__ gb){
    int gt=blockIdx.x*blockDim.x+threadIdx.x; int n=gt>>5; if(n>=NN) return;
    int lane=gt&31,j0=lane<<2;
    float4 fv=(j0<64)?*(const float4*)&g_h[(size_t)n*64+j0]:*(const float4*)&g_h0[(size_t)n*64+j0-64];
    float4 wv=*(const float4*)&gW[j0];
    float s=fv.x*wv.x+fv.y*wv.y+fv.z*wv.z+fv.w*wv.w;
#pragma unroll
    for(int o=16;o;o>>=1) s+=__shfl_xor_sync(0xffffffffu,s,o);
    if(lane==0){ float g=s+gb[0]; g_gate[n]=g; atomicMaxFloat(&g_gmax[gid[n]],g); }
}
__global__ __launch_bounds__(256) void pool_kernel(const int* __restrict__ gid){
    int gt=blockIdx.x*blockDim.x+threadIdx.x; int n=gt>>5; if(n>=NN) return;
    int lane=gt&31; int g=gid[n];
    float gm=g_gmax[g]; if(!isfinite(gm)) gm=0.f;
    float e=expf(g_gate[n]-gm);
    int j0=lane<<2;
    float4 fv=(j0<64)?*(const float4*)&g_h[(size_t)n*64+j0]:*(const float4*)&g_h0[(size_t)n*64+j0-64];
    float* rp=&g_rsum[g*128+j0];
    atomicAdd(rp,e*fv.x); atomicAdd(rp+1,e*fv.y); atomicAdd(rp+2,e*fv.z); atomicAdd(rp+3,e*fv.w);
    if(lane==0) atomicAdd(&g_den[g],e);
}
__global__ void out_kernel(const float* __restrict__ oW,const float* __restrict__ ob,float* __restrict__ out){
    int b=blockIdx.x,tid=threadIdx.x;
    float dn=g_den[b]; float inv=(dn>0.f)?(1.f/dn):0.f;
    float r=g_rsum[b*128+tid]*inv;
    float p0=r*oW[tid*2],p1=r*oW[tid*2+1];
#pragma unroll
    for(int o=16;o;o>>=1){ p0+=__shfl_xor_sync(0xffffffffu,p0,o); p1+=__shfl_xor_sync(0xffffffffu,p1,o); }
    __shared__ float s0[4],s1[4];
    if((tid&31)==0){ s0[tid>>5]=p0; s1[tid>>5]=p1; }
    __syncthreads();
    if(tid==0){ out[b*2]=s0[0]+s0[1]+s0[2]+s0[3]+ob[0]; out[b*2+1]=s1[0]+s1[1]+s1[2]+s1[3]+ob[1]; }
}

// ---------------- host orchestration ---------------------------------------------
extern "C" void kernel_launch(void* const* d_in,const int* in_sizes,int n_in,
                              void* d_out,int out_size){
    const float* ann=(const float*)d_in[0];
    const int* src=(const int*)d_in[1];
    const int* dst=(const int*)d_in[2];
    const int* ety=(const int*)d_in[3];
    const int* gid=(const int*)d_in[4];
    const float* reduce_W=(const float*)d_in[5];
    const float* reduce_b=(const float*)d_in[6];
    const float* edge_W=(const float*)d_in[7];
    const float* edge_b=(const float*)d_in[8];
    const float* gru_Wi=(const float*)d_in[9];
    const float* gru_bi=(const float*)d_in[10];
    const float* gru_Wh=(const float*)d_in[11];
    const float* gru_bh=(const float*)d_in[12];
    const float* gate_W=(const float*)d_in[13];
    const float* gate_b=(const float*)d_in[14];
    const float* out_W=(const float*)d_in[15];
    const float* out_b=(const float*)d_in[16];
    float* out=(float*)d_out;

    cudaFuncSetAttribute(reduce_mma,cudaFuncAttributeMaxDynamicSharedMemorySize,SMB);
    cudaFuncSetAttribute(agg_mma,cudaFuncAttributeMaxDynamicSharedMemorySize,SMB);
    cudaFuncSetAttribute(gru_mma,cudaFuncAttributeMaxDynamicSharedMemorySize,SMB);

    zero_cnt<<<(NN*4+255)/256,256>>>();
    hist_kernel<<<(EE+255)/256,256>>>(dst,ety);
    scan_kernel<<<1,1024>>>();
    fill_kernel<<<(EE+255)/256,256>>>(src,dst,ety);
    pack_mma<<<(65536+255)/256,256>>>(reduce_W,edge_W,gru_Wi,gru_Wh);
    init_pool<<<1,256>>>();

    reduce_mma<<<GRID_M,1024,SMB>>>(ann,reduce_b);
    for(int s=0;s<NSTEPS;++s){
        agg_mma<<<GRID_M,1024,SMB>>>(edge_b);
        gru_mma<<<GRID_M,1024,SMB>>>(gru_bi,gru_bh);
    }
    gate_kernel<<<(NN*32+255)/256,256>>>(gid,gate_W,gate_b);
    pool_kernel<<<(NN*32+255)/256,256>>>(gid);
    out_kernel<<<BB,128>>>(out_W,out_b,out);
}